// round 2
// baseline (speedup 1.0000x reference)
#include <cuda_runtime.h>
#include <cstdint>

// GRU seq2seq: B=512, S=128(enc), P=32, F=O=64, H=1024, IN=128, 159 steps.
// Round 2: double-buffered smem pipeline + 512 threads/CTA, FFMA2 (f32x2).

#define B_    512
#define S_    128
#define P_    32
#define F_    64
#define O_    64
#define H_    1024
#define IN_   128
#define TTOT  159

#define BM 64
#define BN 64
#define BK 16
#define BMP (BM + 4)   // padded row stride (multiple of 4 floats -> 16B aligned)
#define BNP (BN + 4)

typedef unsigned long long ull;

// ---------------- scratch ----------------------------------------------------
__device__ float g_x[TTOT][B_][IN_];
__device__ float g_h[2][B_][H_];
__device__ float g_Wdt[H_][O_];

// ---------------- f32x2 helpers ---------------------------------------------
__device__ __forceinline__ ull pack2(float x, float y) {
    ull r;
    asm("mov.b64 %0, {%1, %2};" : "=l"(r) : "f"(x), "f"(y));
    return r;
}
__device__ __forceinline__ void ffma2(ull& d, ull a, ull b) {
    asm("fma.rn.f32x2 %0, %1, %2, %0;" : "+l"(d) : "l"(a), "l"(b));
}
__device__ __forceinline__ float2 unpack2(ull v) {
    float2 f;
    asm("mov.b64 {%0, %1}, %2;" : "=f"(f.x), "=f"(f.y) : "l"(v));
    return f;
}
__device__ __forceinline__ float sigf(float x)  { return 1.f / (1.f + __expf(-x)); }
__device__ __forceinline__ float tanhf_(float x){ return 1.f - 2.f / (1.f + __expf(2.f * x)); }

// ---------------- pack kernel ------------------------------------------------
__global__ void pack_kernel(const float* __restrict__ feats,
                            const float* __restrict__ labels,
                            const float* __restrict__ Wd) {
    long idx = (long)blockIdx.x * 256 + threadIdx.x;
    const long N1 = (long)TTOT * B_ * F_;
    const long N2 = (long)S_   * B_ * O_;
    const long N3 = (long)B_ * H_;
    const long N4 = (long)H_ * O_;
    if (idx < N1) {
        int t = (int)(idx / (B_ * F_));
        int r = (int)(idx % (B_ * F_));
        int b = r / F_, c = r % F_;
        g_x[t][b][c] = feats[((long)b * TTOT + t) * F_ + c];
        return;
    }
    idx -= N1;
    if (idx < N2) {
        int t = (int)(idx / (B_ * O_));
        int r = (int)(idx % (B_ * O_));
        int b = r / O_, c = r % O_;
        g_x[t][b][F_ + c] = labels[((long)b * S_ + t) * O_ + c];
        return;
    }
    idx -= N2;
    if (idx < N3) { ((float*)g_h)[idx] = 0.f; return; }
    idx -= N3;
    if (idx < N4) {
        int k = (int)(idx / O_), o = (int)(idx % O_);
        g_Wdt[k][o] = Wd[(long)o * H_ + k];
    }
}

// ---------------- GEMM phase (double-buffered) -------------------------------
// A: [rows][ld] K-major activations; W: [3H][ld] K-major weights.
// Accumulates r/z into aR/aZ and the phase's n-gate into aN.
template<int KTILES>
__device__ __forceinline__ void gemm_phase(
    const float* __restrict__ A, const float* __restrict__ W, int ld,
    int bm0, int bn0, int lr, int lk2, int tx, int ty,
    float (*As)[BK][BMP], float (*Bs)[3][BK][BNP],
    ull (&aR)[2][2], ull (&aZ)[2][2], ull (&aN)[2][2])
{
    const float* ga  = &A[(bm0 + lr) * ld + lk2];
    const float* gb0 = &W[(0 * H_ + bn0 + lr) * ld + lk2];
    const float* gb1 = &W[(1 * H_ + bn0 + lr) * ld + lk2];
    const float* gb2 = &W[(2 * H_ + bn0 + lr) * ld + lk2];

    float2 ra  = *(const float2*)(ga);
    float2 rb0 = *(const float2*)(gb0);
    float2 rb1 = *(const float2*)(gb1);
    float2 rb2 = *(const float2*)(gb2);

    // buffer 0 may still be read by the previous phase's last tile
    __syncthreads();
    As[0][lk2][lr] = ra.x;  As[0][lk2 + 1][lr] = ra.y;
    Bs[0][0][lk2][lr] = rb0.x; Bs[0][0][lk2 + 1][lr] = rb0.y;
    Bs[0][1][lk2][lr] = rb1.x; Bs[0][1][lk2 + 1][lr] = rb1.y;
    Bs[0][2][lk2][lr] = rb2.x; Bs[0][2][lk2 + 1][lr] = rb2.y;
    __syncthreads();

    int buf = 0;
    for (int t = 0; t < KTILES; ++t) {
        const bool more = (t + 1 < KTILES);
        if (more) {
            const int kt = (t + 1) * BK;
            ra  = *(const float2*)(ga  + kt);
            rb0 = *(const float2*)(gb0 + kt);
            rb1 = *(const float2*)(gb1 + kt);
            rb2 = *(const float2*)(gb2 + kt);
        }
        // compute current buffer
        #pragma unroll
        for (int k = 0; k < BK; ++k) {
            float2 a2 = *(const float2*)&As[buf][k][ty * 2];
            ull ax = pack2(a2.x, a2.x);
            ull ay = pack2(a2.y, a2.y);
            const ull* bR = (const ull*)&Bs[buf][0][k][tx * 4];
            const ull* bZ = (const ull*)&Bs[buf][1][k][tx * 4];
            const ull* bN = (const ull*)&Bs[buf][2][k][tx * 4];
            ull br0 = bR[0], br1 = bR[1];
            ull bz0 = bZ[0], bz1 = bZ[1];
            ull bn0p = bN[0], bn1p = bN[1];
            ffma2(aR[0][0], ax, br0); ffma2(aR[0][1], ax, br1);
            ffma2(aR[1][0], ay, br0); ffma2(aR[1][1], ay, br1);
            ffma2(aZ[0][0], ax, bz0); ffma2(aZ[0][1], ax, bz1);
            ffma2(aZ[1][0], ay, bz0); ffma2(aZ[1][1], ay, bz1);
            ffma2(aN[0][0], ax, bn0p); ffma2(aN[0][1], ax, bn1p);
            ffma2(aN[1][0], ay, bn0p); ffma2(aN[1][1], ay, bn1p);
        }
        if (more) {
            const int nb = buf ^ 1;
            As[nb][lk2][lr] = ra.x;  As[nb][lk2 + 1][lr] = ra.y;
            Bs[nb][0][lk2][lr] = rb0.x; Bs[nb][0][lk2 + 1][lr] = rb0.y;
            Bs[nb][1][lk2][lr] = rb1.x; Bs[nb][1][lk2 + 1][lr] = rb1.y;
            Bs[nb][2][lk2][lr] = rb2.x; Bs[nb][2][lk2 + 1][lr] = rb2.y;
            __syncthreads();
            buf = nb;
        }
    }
}

// ---------------- fused GRU step kernel -------------------------------------
__global__ __launch_bounds__(512)
void gru_step_kernel(int t, int cur,
                     const float* __restrict__ Wi, const float* __restrict__ Wh,
                     const float* __restrict__ bi, const float* __restrict__ bh)
{
    __shared__ float As[2][BK][BMP];
    __shared__ float Bs[2][3][BK][BNP];

    const int tid = threadIdx.x;
    const int tx = tid % 16;          // 16 N-groups of 4 floats
    const int ty = tid / 16;          // 32 M-groups of 2 rows
    const int lr  = tid / 8;          // 0..63 load row
    const int lk2 = (tid % 8) * 2;    // 0,2,..,14 load k offset
    const int bm0 = blockIdx.x * BM;
    const int bn0 = blockIdx.y * BN;

    const float* h_in  = &g_h[cur][0][0];
    float*       h_out = &g_h[cur ^ 1][0][0];
    const float* xt    = &g_x[t][0][0];

    ull aR[2][2], aZ[2][2], aIN[2][2], aHN[2][2];
    #pragma unroll
    for (int i = 0; i < 2; ++i)
        #pragma unroll
        for (int j = 0; j < 2; ++j) {
            aR[i][j] = 0ULL; aZ[i][j] = 0ULL;
            aIN[i][j] = 0ULL; aHN[i][j] = 0ULL;
        }

    gemm_phase<IN_ / BK>(xt,   Wi, IN_, bm0, bn0, lr, lk2, tx, ty, As, Bs,
                         aR, aZ, aIN);
    gemm_phase<H_ / BK>(h_in, Wh, H_,  bm0, bn0, lr, lk2, tx, ty, As, Bs,
                        aR, aZ, aHN);

    // epilogue: gates + state update
    #pragma unroll
    for (int ii = 0; ii < 2; ++ii) {
        const int b = bm0 + ty * 2 + ii;
        #pragma unroll
        for (int jp = 0; jp < 2; ++jp) {
            float2 r2  = unpack2(aR[ii][jp]);
            float2 z2  = unpack2(aZ[ii][jp]);
            float2 in2 = unpack2(aIN[ii][jp]);
            float2 hn2 = unpack2(aHN[ii][jp]);
            #pragma unroll
            for (int u = 0; u < 2; ++u) {
                const int j = bn0 + tx * 4 + jp * 2 + u;
                float rs = (u == 0) ? r2.x  : r2.y;
                float zs = (u == 0) ? z2.x  : z2.y;
                float is = (u == 0) ? in2.x : in2.y;
                float hs = (u == 0) ? hn2.x : hn2.y;
                float rv = sigf(rs + bi[j] + bh[j]);
                float zv = sigf(zs + bi[H_ + j] + bh[H_ + j]);
                float hn = hs + bh[2 * H_ + j];
                float nv = tanhf_(is + bi[2 * H_ + j] + rv * hn);
                float ho = h_in[b * H_ + j];
                h_out[b * H_ + j] = nv + zv * (ho - nv);
            }
        }
    }
}

// ---------------- ps = h @ Wd.T + bd ----------------------------------------
__global__ __launch_bounds__(256)
void ps_kernel(int cur, const float* __restrict__ bd,
               float* __restrict__ out_slot, int xslot)
{
    __shared__ float hsm[4][H_];
    __shared__ float red[4][4][O_];
    const int tid = threadIdx.x;
    const int o = tid % 64;
    const int s = tid / 64;
    const int b0 = blockIdx.x * 4;
    const float* h = &g_h[cur][0][0];

    for (int i = tid; i < 4 * H_; i += 256) {
        int bb = i / H_, k = i % H_;
        hsm[bb][k] = h[(b0 + bb) * H_ + k];
    }
    __syncthreads();

    float acc0 = 0.f, acc1 = 0.f, acc2 = 0.f, acc3 = 0.f;
    const int k0 = s * (H_ / 4);
    for (int k = k0; k < k0 + (H_ / 4); ++k) {
        float w = g_Wdt[k][o];
        acc0 += hsm[0][k] * w;
        acc1 += hsm[1][k] * w;
        acc2 += hsm[2][k] * w;
        acc3 += hsm[3][k] * w;
    }
    red[s][0][o] = acc0; red[s][1][o] = acc1;
    red[s][2][o] = acc2; red[s][3][o] = acc3;
    __syncthreads();

    if (s == 0) {
        #pragma unroll
        for (int bb = 0; bb < 4; ++bb) {
            float v = red[0][bb][o] + red[1][bb][o] +
                      red[2][bb][o] + red[3][bb][o] + bd[o];
            out_slot[(b0 + bb) * O_ + o] = v;
            if (xslot >= 0) g_x[xslot][b0 + bb][F_ + o] = v;
        }
    }
}

// ---------------- launch -----------------------------------------------------
extern "C" void kernel_launch(void* const* d_in, const int* in_sizes, int n_in,
                              void* d_out, int out_size)
{
    const float* feats  = (const float*)d_in[0];
    const float* labels = (const float*)d_in[1];
    const float* Wi     = (const float*)d_in[2];
    const float* Wh     = (const float*)d_in[3];
    const float* bi     = (const float*)d_in[4];
    const float* bh     = (const float*)d_in[5];
    const float* Wd     = (const float*)d_in[6];
    const float* bd     = (const float*)d_in[7];
    float* out = (float*)d_out;

    {
        const long total = (long)TTOT * B_ * F_ + (long)S_ * B_ * O_ +
                           (long)B_ * H_ + (long)H_ * O_;
        const int blocks = (int)((total + 255) / 256);
        pack_kernel<<<blocks, 256>>>(feats, labels, Wd);
    }

    dim3 grid(B_ / BM, H_ / BN);   // 8 x 16 = 128 CTAs
    int cur = 0;

    for (int t = 0; t < S_; ++t) {
        gru_step_kernel<<<grid, 512>>>(t, cur, Wi, Wh, bi, bh);
        cur ^= 1;
    }
    ps_kernel<<<B_ / 4, 256>>>(cur, bd, out, S_);

    for (int i = 0; i < P_ - 1; ++i) {
        gru_step_kernel<<<grid, 512>>>(S_ + i, cur, Wi, Wh, bi, bh);
        cur ^= 1;
        ps_kernel<<<B_ / 4, 256>>>(cur, bd,
                                   out + (long)(i + 1) * B_ * O_,
                                   (i < P_ - 2) ? (S_ + 1 + i) : -1);
    }
}

// round 7
// speedup vs baseline: 3.1304x; 3.1304x over previous
#include <cuda_runtime.h>
#include <cuda_bf16.h>
#include <cstdint>

// GRU seq2seq via mma.sync bf16 hi/lo split (portable sm_80+ PTX; no tcgen05).
// B=512, S=128, P=32, F=O=64, H=1024, IN=128, K=1152, 159 steps.

#define B_    512
#define S_    128
#define P_    32
#define F_    64
#define O_    64
#define H_    1024
#define IN_   128
#define KTOT  1152
#define TTOT  159
#define BM    128
#define BN    32
#define NCH   36      // K chunks of 32
#define XCH   4       // first 4 chunks are the x-part (K=128)

// stage layout (bytes)
#define A_HI 0
#define A_LO 8192
#define B_HI 16384
#define B_LO 22528
#define STAGE 28672
#define SMEM_DYN (2 * STAGE)

typedef __nv_bfloat16 bf16;

// ---------------- device scratch --------------------------------------------
__device__ bf16  g_x_hi[TTOT][B_][IN_];
__device__ bf16  g_x_lo[TTOT][B_][IN_];
__device__ bf16  g_w_hi[3 * H_][KTOT];
__device__ bf16  g_w_lo[3 * H_][KTOT];
__device__ float g_h[2][B_][H_];
__device__ bf16  g_h_hi[2][B_][H_];
__device__ bf16  g_h_lo[2][B_][H_];
__device__ float g_Wdt[H_][O_];
__device__ float g_brz[2 * H_];
__device__ float g_bin[H_];
__device__ float g_bhn[H_];

// ---------------- helpers ----------------------------------------------------
__device__ __forceinline__ uint32_t smem_u32(const void* p) {
    uint32_t a;
    asm("{ .reg .u64 t; cvta.to.shared.u64 t, %1; cvt.u32.u64 %0, t; }"
        : "=r"(a) : "l"(p));
    return a;
}
__device__ __forceinline__ void cp16(uint32_t dst, const void* src) {
    asm volatile("cp.async.cg.shared.global [%0], [%1], 16;"
                 :: "r"(dst), "l"(src) : "memory");
}
__device__ __forceinline__ void cp_commit() {
    asm volatile("cp.async.commit_group;" ::: "memory");
}
template<int N>
__device__ __forceinline__ void cp_wait() {
    asm volatile("cp.async.wait_group %0;" :: "n"(N) : "memory");
}
__device__ __forceinline__ void ldsm4(uint32_t* r, uint32_t addr) {
    asm volatile("ldmatrix.sync.aligned.m8n8.x4.shared.b16 "
                 "{%0,%1,%2,%3}, [%4];"
                 : "=r"(r[0]), "=r"(r[1]), "=r"(r[2]), "=r"(r[3])
                 : "r"(addr));
}
__device__ __forceinline__ void mma16816(float* c, const uint32_t* a,
                                         uint32_t b0, uint32_t b1) {
    asm volatile(
        "mma.sync.aligned.m16n8k16.row.col.f32.bf16.bf16.f32 "
        "{%0,%1,%2,%3}, {%4,%5,%6,%7}, {%8,%9}, {%0,%1,%2,%3};"
        : "+f"(c[0]), "+f"(c[1]), "+f"(c[2]), "+f"(c[3])
        : "r"(a[0]), "r"(a[1]), "r"(a[2]), "r"(a[3]), "r"(b0), "r"(b1));
}
// 16B-chunk XOR swizzle within 64B rows (conflict-free for 8-row ldmatrix phases)
__device__ __forceinline__ uint32_t swz(int row, int kc) {
    return (uint32_t)(row * 64 + ((kc ^ ((row >> 1) & 3)) << 4));
}
__device__ __forceinline__ float sigf(float x)  { return 1.f / (1.f + __expf(-x)); }
__device__ __forceinline__ float tanhf_(float x){ return 1.f - 2.f / (1.f + __expf(2.f * x)); }

// ---------------- pack kernel ------------------------------------------------
__global__ void pack_kernel(const float* __restrict__ feats,
                            const float* __restrict__ labels,
                            const float* __restrict__ Wi,
                            const float* __restrict__ Wh,
                            const float* __restrict__ bi,
                            const float* __restrict__ bh,
                            const float* __restrict__ Wd) {
    long idx = (long)blockIdx.x * 256 + threadIdx.x;
    const long N1 = (long)TTOT * B_ * F_;
    const long N2 = (long)S_ * B_ * O_;
    const long N3 = (long)3 * H_ * KTOT;
    const long N4 = (long)B_ * H_;
    const long N5 = (long)H_ * O_;
    const long N6 = 4096;
    if (idx < N1) {
        int t = (int)(idx / (B_ * F_));
        int r = (int)(idx % (B_ * F_));
        int b = r / F_, c = r % F_;
        float v = feats[((long)b * TTOT + t) * F_ + c];
        bf16 h = __float2bfloat16(v);
        g_x_hi[t][b][c] = h;
        g_x_lo[t][b][c] = __float2bfloat16(v - __bfloat162float(h));
        return;
    }
    idx -= N1;
    if (idx < N2) {
        int t = (int)(idx / (B_ * O_));
        int r = (int)(idx % (B_ * O_));
        int b = r / O_, c = r % O_;
        float v = labels[((long)b * S_ + t) * O_ + c];
        bf16 h = __float2bfloat16(v);
        g_x_hi[t][b][F_ + c] = h;
        g_x_lo[t][b][F_ + c] = __float2bfloat16(v - __bfloat162float(h));
        return;
    }
    idx -= N2;
    if (idx < N3) {
        int n = (int)(idx / KTOT), k = (int)(idx % KTOT);
        float v = (k < IN_) ? Wi[(long)n * IN_ + k]
                            : Wh[(long)n * H_ + (k - IN_)];
        bf16 h = __float2bfloat16(v);
        g_w_hi[n][k] = h;
        g_w_lo[n][k] = __float2bfloat16(v - __bfloat162float(h));
        return;
    }
    idx -= N3;
    if (idx < N4) {
        int b = (int)(idx / H_), j = (int)(idx % H_);
        g_h[0][b][j] = 0.f;
        g_h_hi[0][b][j] = __float2bfloat16(0.f);
        g_h_lo[0][b][j] = __float2bfloat16(0.f);
        return;
    }
    idx -= N4;
    if (idx < N5) {
        int k = (int)(idx / O_), o = (int)(idx % O_);
        g_Wdt[k][o] = Wd[(long)o * H_ + k];
        return;
    }
    idx -= N5;
    if (idx < N6) {
        int i = (int)idx;
        if (i < 2048)      g_brz[i] = bi[i] + bh[i];
        else if (i < 3072) g_bin[i - 2048] = bi[i];
        else               g_bhn[i - 3072] = bh[i - 1024];
    }
}

// ---------------- compute one K-chunk (2 k16 steps) --------------------------
// G2 = accumulator group for the n-gate this chunk (2 = IN, 3 = HN).
template<int G2>
__device__ __forceinline__ void compute_chunk(
    const char* st, int lane, int mw, int nw, float (&acc)[4][2][2][4])
{
    const uint32_t ab = smem_u32(st + A_HI);
    const uint32_t bb = smem_u32(st + B_HI);
    #pragma unroll
    for (int ks = 0; ks < 2; ++ks) {
        uint32_t Ah[2][4], Al[2][4];
        #pragma unroll
        for (int mi = 0; mi < 2; ++mi) {
            const int arow = mw * 32 + mi * 16 + (lane & 15);
            const int kc = ks * 2 + (lane >> 4);
            const uint32_t off = swz(arow, kc);
            ldsm4(Ah[mi], ab + off);
            ldsm4(Al[mi], ab + (A_LO - A_HI) + off);
        }
        #pragma unroll
        for (int g = 0; g < 3; ++g) {
            const int grp = (g == 2) ? G2 : g;
            const int brow = g * 32 + nw * 16 + ((lane >> 4) << 3) + (lane & 7);
            const int kc = ks * 2 + ((lane >> 3) & 1);
            const uint32_t off = swz(brow, kc);
            uint32_t Bh[4], Bl[4];
            ldsm4(Bh, bb + off);
            ldsm4(Bl, bb + (B_LO - B_HI) + off);
            #pragma unroll
            for (int mi = 0; mi < 2; ++mi) {
                #pragma unroll
                for (int nj = 0; nj < 2; ++nj) {
                    float* C = acc[grp][mi][nj];
                    mma16816(C, Ah[mi], Bh[nj * 2], Bh[nj * 2 + 1]);
                    mma16816(C, Al[mi], Bh[nj * 2], Bh[nj * 2 + 1]);
                    mma16816(C, Ah[mi], Bl[nj * 2], Bl[nj * 2 + 1]);
                }
            }
        }
    }
}

// ---------------- fused GRU step (mma.sync) ----------------------------------
__global__ __launch_bounds__(256)
void gru_step_mma(int t, int cur) {
    extern __shared__ char sm[];
    const int tid = threadIdx.x;
    const int lane = tid & 31, wid = tid >> 5;
    const int mw = wid & 3, nw = wid >> 2;
    const int bm0 = blockIdx.x * BM;
    const int bn0 = blockIdx.y * BN;
    const int nxt = cur ^ 1;

    float acc[4][2][2][4];
    #pragma unroll
    for (int a = 0; a < 4; ++a)
        #pragma unroll
        for (int b = 0; b < 2; ++b)
            #pragma unroll
            for (int c = 0; c < 2; ++c)
                #pragma unroll
                for (int d = 0; d < 4; ++d) acc[a][b][c][d] = 0.f;

    // ---- async chunk loader ----
    auto load_chunk = [&](int ch) {
        char* st = sm + (ch & 1) * STAGE;
        const int k0 = ch * 32;
        // A: 1024 16B-chunks (hi+lo)
        #pragma unroll
        for (int i = 0; i < 4; ++i) {
            const int c = tid + i * 256;
            const int term = c >> 9;
            const int rem = c & 511;
            const int row = rem >> 2, kc = rem & 3;
            const bf16* src;
            if (ch < XCH) {
                const bf16* base = term ? &g_x_lo[t][0][0] : &g_x_hi[t][0][0];
                src = base + (long)(bm0 + row) * IN_ + k0 + kc * 8;
            } else {
                const bf16* base = term ? &g_h_lo[cur][0][0] : &g_h_hi[cur][0][0];
                src = base + (long)(bm0 + row) * H_ + (k0 - IN_) + kc * 8;
            }
            cp16(smem_u32(st + (term ? A_LO : A_HI)) + swz(row, kc), src);
        }
        // B: 768 16B-chunks (hi+lo), rows = 3 gates x 32 cols
        #pragma unroll
        for (int i = 0; i < 3; ++i) {
            const int c = tid + i * 256;
            const int term = (c >= 384);
            const int rem = c - term * 384;
            const int row = rem >> 2, kc = rem & 3;
            const int grow = (row >> 5) * H_ + bn0 + (row & 31);
            const bf16* base = term ? &g_w_lo[0][0] : &g_w_hi[0][0];
            const bf16* src = base + (long)grow * KTOT + k0 + kc * 8;
            cp16(smem_u32(st + (term ? B_LO : B_HI)) + swz(row, kc), src);
        }
    };

    load_chunk(0);
    cp_commit();

    for (int ch = 0; ch < NCH; ++ch) {
        if (ch + 1 < NCH) {
            load_chunk(ch + 1);
            cp_commit();
            cp_wait<1>();
        } else {
            cp_wait<0>();
        }
        __syncthreads();
        const char* st = sm + (ch & 1) * STAGE;
        if (ch < XCH) compute_chunk<2>(st, lane, mw, nw, acc);
        else          compute_chunk<3>(st, lane, mw, nw, acc);
        __syncthreads();
    }

    // ---- epilogue: gates + state update (all in-register) ----
    const int l4 = lane >> 2;
    const int l2 = (lane & 3) * 2;
    #pragma unroll
    for (int mi = 0; mi < 2; ++mi) {
        #pragma unroll
        for (int nj = 0; nj < 2; ++nj) {
            const int j0 = bn0 + nw * 16 + nj * 8 + l2;
            #pragma unroll
            for (int rh = 0; rh < 2; ++rh) {
                const int b = bm0 + mw * 32 + mi * 16 + l4 + rh * 8;
                const float2 hold = *(const float2*)&g_h[cur][b][j0];
                float hv[2]; bf16 hh[2], hl[2];
                #pragma unroll
                for (int u = 0; u < 2; ++u) {
                    const int j = j0 + u;
                    const int ai = rh * 2 + u;
                    float rv = sigf(acc[0][mi][nj][ai] + g_brz[j]);
                    float zv = sigf(acc[1][mi][nj][ai] + g_brz[H_ + j]);
                    float nv = tanhf_(acc[2][mi][nj][ai] + g_bin[j] +
                                      rv * (acc[3][mi][nj][ai] + g_bhn[j]));
                    float ho = (u == 0) ? hold.x : hold.y;
                    float v = nv + zv * (ho - nv);
                    hv[u] = v;
                    hh[u] = __float2bfloat16(v);
                    hl[u] = __float2bfloat16(v - __bfloat162float(hh[u]));
                }
                *(float2*)&g_h[nxt][b][j0] = make_float2(hv[0], hv[1]);
                *(uint32_t*)&g_h_hi[nxt][b][j0] = *(uint32_t*)hh;
                *(uint32_t*)&g_h_lo[nxt][b][j0] = *(uint32_t*)hl;
            }
        }
    }
}

// ---------------- ps = h @ Wd.T + bd ----------------------------------------
__global__ __launch_bounds__(256)
void ps_kernel(int cur, const float* __restrict__ bd,
               float* __restrict__ out_slot, int xslot)
{
    __shared__ float hsm[4][H_];
    __shared__ float red[4][4][O_];
    const int tid = threadIdx.x;
    const int o = tid % 64;
    const int s = tid / 64;
    const int b0 = blockIdx.x * 4;
    const float* h = &g_h[cur][0][0];

    for (int i = tid; i < 4 * H_; i += 256) {
        int bb = i / H_, k = i % H_;
        hsm[bb][k] = h[(b0 + bb) * H_ + k];
    }
    __syncthreads();

    float a0 = 0.f, a1 = 0.f, a2 = 0.f, a3 = 0.f;
    const int k0 = s * (H_ / 4);
    for (int k = k0; k < k0 + (H_ / 4); ++k) {
        float w = g_Wdt[k][o];
        a0 += hsm[0][k] * w;
        a1 += hsm[1][k] * w;
        a2 += hsm[2][k] * w;
        a3 += hsm[3][k] * w;
    }
    red[s][0][o] = a0; red[s][1][o] = a1;
    red[s][2][o] = a2; red[s][3][o] = a3;
    __syncthreads();

    if (s == 0) {
        #pragma unroll
        for (int bb = 0; bb < 4; ++bb) {
            float v = red[0][bb][o] + red[1][bb][o] +
                      red[2][bb][o] + red[3][bb][o] + bd[o];
            out_slot[(b0 + bb) * O_ + o] = v;
            if (xslot >= 0) {
                bf16 h2 = __float2bfloat16(v);
                g_x_hi[xslot][b0 + bb][F_ + o] = h2;
                g_x_lo[xslot][b0 + bb][F_ + o] =
                    __float2bfloat16(v - __bfloat162float(h2));
            }
        }
    }
}

// ---------------- launch -----------------------------------------------------
extern "C" void kernel_launch(void* const* d_in, const int* in_sizes, int n_in,
                              void* d_out, int out_size)
{
    const float* feats  = (const float*)d_in[0];
    const float* labels = (const float*)d_in[1];
    const float* Wi     = (const float*)d_in[2];
    const float* Wh     = (const float*)d_in[3];
    const float* bi     = (const float*)d_in[4];
    const float* bh     = (const float*)d_in[5];
    const float* Wd     = (const float*)d_in[6];
    const float* bd     = (const float*)d_in[7];
    float* out = (float*)d_out;

    cudaFuncSetAttribute(gru_step_mma,
                         cudaFuncAttributeMaxDynamicSharedMemorySize, SMEM_DYN);

    {
        const long total = (long)TTOT * B_ * F_ + (long)S_ * B_ * O_ +
                           (long)3 * H_ * KTOT + (long)B_ * H_ +
                           (long)H_ * O_ + 4096;
        const int blocks = (int)((total + 255) / 256);
        pack_kernel<<<blocks, 256>>>(feats, labels, Wi, Wh, bi, bh, Wd);
    }

    dim3 grid(B_ / BM, H_ / BN);   // 4 x 32 = 128 CTAs
    int cur = 0;

    for (int t = 0; t < S_; ++t) {
        gru_step_mma<<<grid, 256, SMEM_DYN>>>(t, cur);
        cur ^= 1;
    }
    ps_kernel<<<B_ / 4, 256>>>(cur, bd, out, S_);

    for (int i = 0; i < P_ - 1; ++i) {
        gru_step_mma<<<grid, 256, SMEM_DYN>>>(S_ + i, cur);
        cur ^= 1;
        ps_kernel<<<B_ / 4, 256>>>(cur, bd,
                                   out + (long)(i + 1) * B_ * O_,
                                   (i < P_ - 2) ? (S_ + 1 + i) : -1);
    }
}